// round 1
// baseline (speedup 1.0000x reference)
#include <cuda_runtime.h>
#include <cstdint>

// Problem constants (fixed by the reference):
//   B=8, C=16, H=512, W=512, M=N=15
//   K:     [128, 16, 16]  float32   (B*C = 128 "bc" slices)
//   basis: [262144, 16, 16] float32 (separable: basis[h*W+w,p,q] = Bu[h,p]*Bv[w,q])
//   out:   [1, 8, 16, 512, 512] float32 = 33,554,432 elements
//
// Strategy (separable factorization):
//   Bu[h,p] = sum_q basis[h*W + 0, p, q]   (partition of unity in q)
//   Bv[w,q] = sum_p basis[0*W + w, p, q]   (partition of unity in p)
//   T[bc,p,w]  = sum_q K[bc,p,q] * Bv[w,q]
//   out[bc,h,w] = sum_p Bu[h,p] * T[bc,p,w]

#define HH 512
#define WW 512
#define PP 16   // M+1
#define QQ 16   // N+1
#define BC 128  // B*C

// Scratch (static device globals; no runtime allocation allowed)
__device__ float g_Bu[HH * PP];            //  32 KB
__device__ float g_Bv[WW * QQ];            //  32 KB
__device__ float g_T[BC * PP * WW];        //  16 MB

// ---------------------------------------------------------------------------
// Kernel A: extract Bu and Bv from the basis tensor via partition-of-unity sums
// 16384 threads total: first 8192 -> Bu[h][p], next 8192 -> Bv[w][q]
// ---------------------------------------------------------------------------
__global__ void extract_factors(const float* __restrict__ basis) {
    int i = blockIdx.x * blockDim.x + threadIdx.x;
    if (i < HH * PP) {
        int h = i >> 4;
        int p = i & 15;
        // basis row n = h*W (w = 0), sum over q
        const float* row = basis + (size_t)h * WW * (PP * QQ) + p * QQ;
        float s = 0.f;
        #pragma unroll
        for (int q = 0; q < QQ; ++q) s += row[q];
        g_Bu[i] = s;
    } else if (i < 2 * HH * PP) {
        int j = i - HH * PP;
        int w = j >> 4;
        int q = j & 15;
        // basis row n = w (h = 0), sum over p (stride QQ)
        const float* col = basis + (size_t)w * (PP * QQ) + q;
        float s = 0.f;
        #pragma unroll
        for (int p = 0; p < PP; ++p) s += col[p * QQ];
        g_Bv[w * QQ + q] = s;
    }
}

// ---------------------------------------------------------------------------
// Kernel B: T[bc][p][w] = sum_q K[bc][p][q] * Bv[w][q]
// grid.x = BC*PP = 2048 blocks, 512 threads (one per w)
// ---------------------------------------------------------------------------
__global__ void stage1(const float* __restrict__ K) {
    int bcp = blockIdx.x;          // bc*16 + p
    int w = threadIdx.x;           // 0..511

    __shared__ float sk[QQ];
    if (threadIdx.x < QQ) sk[threadIdx.x] = K[(size_t)bcp * QQ + threadIdx.x];
    __syncthreads();

    const float4* bv = reinterpret_cast<const float4*>(g_Bv + (size_t)w * QQ);
    float acc = 0.f;
    #pragma unroll
    for (int q4 = 0; q4 < 4; ++q4) {
        float4 v = bv[q4];
        acc += sk[q4 * 4 + 0] * v.x;
        acc += sk[q4 * 4 + 1] * v.y;
        acc += sk[q4 * 4 + 2] * v.z;
        acc += sk[q4 * 4 + 3] * v.w;
    }
    g_T[(size_t)bcp * WW + w] = acc;
}

// ---------------------------------------------------------------------------
// Kernel C: out[bc][h][w] = sum_p Bu[h][p] * T[bc][p][w]
// grid = (H/ROWS, BC). 128 threads; thread t owns float4 of w (w = 4t..4t+3).
// T[bc][p][w4] cached in 64 registers, reused across ROWS h-rows.
// Bu tile staged in SMEM, broadcast-read per row.
// ---------------------------------------------------------------------------
#define ROWS 64

__global__ __launch_bounds__(128) void stage2(float* __restrict__ out) {
    int bc = blockIdx.y;
    int h0 = blockIdx.x * ROWS;
    int t = threadIdx.x;  // 0..127 -> float4 column

    // Load this bc's T slice for our w4 column: 16 float4 = 64 regs
    const float4* Tp = reinterpret_cast<const float4*>(g_T + (size_t)bc * PP * WW);
    float4 Tv[PP];
    #pragma unroll
    for (int p = 0; p < PP; ++p) Tv[p] = Tp[p * (WW / 4) + t];

    // Stage Bu rows [h0, h0+ROWS) into SMEM
    __shared__ float sBu[ROWS * PP];
    #pragma unroll
    for (int i = t; i < ROWS * PP; i += 128) sBu[i] = g_Bu[h0 * PP + i];
    __syncthreads();

    float4* o = reinterpret_cast<float4*>(out + (size_t)bc * HH * WW + (size_t)h0 * WW);

    #pragma unroll 4
    for (int r = 0; r < ROWS; ++r) {
        float4 acc = make_float4(0.f, 0.f, 0.f, 0.f);
        #pragma unroll
        for (int p = 0; p < PP; ++p) {
            float b = sBu[r * PP + p];
            acc.x = fmaf(b, Tv[p].x, acc.x);
            acc.y = fmaf(b, Tv[p].y, acc.y);
            acc.z = fmaf(b, Tv[p].z, acc.z);
            acc.w = fmaf(b, Tv[p].w, acc.w);
        }
        o[r * (WW / 4) + t] = acc;
    }
}

// ---------------------------------------------------------------------------
extern "C" void kernel_launch(void* const* d_in, const int* in_sizes, int n_in,
                              void* d_out, int out_size) {
    const float* K     = (const float*)d_in[0];  // [128,16,16]
    const float* basis = (const float*)d_in[1];  // [262144,16,16]
    float* out = (float*)d_out;                  // [1,8,16,512,512]

    (void)in_sizes; (void)n_in; (void)out_size;

    // A: extract Bu, Bv  (16384 threads)
    extract_factors<<<64, 256>>>(basis);

    // B: T = K x Bv
    stage1<<<BC * PP, WW>>>(K);

    // C: out = Bu x T
    dim3 grid(HH / ROWS, BC);
    stage2<<<grid, 128>>>(out);
}

// round 2
// speedup vs baseline: 1.0609x; 1.0609x over previous
#include <cuda_runtime.h>
#include <cstdint>

// Problem constants:
//   B=8, C=16, H=512, W=512, M=N=15
//   K:     [128, 16, 16]  float32
//   basis: [262144, 16, 16] float32 (separable: basis[h*W+w,p,q] = Bu[h,p]*Bv[w,q])
//   out:   [128, 512, 512] float32
//
// Separable factorization:
//   Bu[h,p] = sum_q basis[h*W, p, q]     (partition of unity in q)
//   Bv[w,q] = sum_p basis[w,    p, q]    (partition of unity in p)
//   out[bc,h,w] = sum_p Bu[h,p] * (sum_q K[bc,p,q] * Bv[w,q])
//
// Fused kernel: each block recomputes T[bc,p,w4] in registers (cheap), then
// runs the h-loop with packed fma.rn.f32x2 (FFMA2) fed by LDS.64 of
// pre-duplicated Bu pairs.

#define HH 512
#define WW 512
#define PP 16
#define QQ 16
#define BC 128
#define ROWS 128

__device__ float g_Bu[HH * PP];   // 32 KB
__device__ float g_Bv[WW * QQ];   // 32 KB

// ---------------------------------------------------------------------------
// Kernel A: extract Bu and Bv.
//   blocks 0..63  : Bu — 8 warps/block, one warp per h row (coalesced + shfl)
//   blocks 64..95 : Bv — 16 w rows/block via contiguous 16KB smem stage
// ---------------------------------------------------------------------------
__global__ __launch_bounds__(256) void extract_factors(const float* __restrict__ basis) {
    int tid = threadIdx.x;
    if (blockIdx.x < 64) {
        int warp = tid >> 5, lane = tid & 31;
        int h = blockIdx.x * 8 + warp;
        // row n = h*W (w=0): 256 contiguous floats; lane covers [8*lane, 8*lane+8)
        const float4* r4 = reinterpret_cast<const float4*>(basis + (size_t)h * WW * (PP * QQ));
        float4 a = r4[lane * 2];
        float4 b = r4[lane * 2 + 1];
        float s = (a.x + a.y) + (a.z + a.w) + (b.x + b.y) + (b.z + b.w);
        // lanes (2k, 2k+1) together cover p = k's 16 q values
        s += __shfl_xor_sync(0xffffffffu, s, 1);
        if ((lane & 1) == 0) g_Bu[h * PP + (lane >> 1)] = s;
    } else {
        __shared__ float sb[16 * PP * QQ];  // 16 w-rows, 16 KB
        int blk = blockIdx.x - 64;
        int w0 = blk * 16;
        const float4* src = reinterpret_cast<const float4*>(basis + (size_t)w0 * (PP * QQ));
        float4* dst = reinterpret_cast<float4*>(sb);
        #pragma unroll
        for (int i = tid; i < 16 * PP * QQ / 4; i += 256) dst[i] = src[i];
        __syncthreads();
        int wl = tid >> 4, q = tid & 15;
        float s = 0.f;
        #pragma unroll
        for (int p = 0; p < PP; ++p) s += sb[wl * (PP * QQ) + p * QQ + q];
        g_Bv[(w0 + wl) * QQ + q] = s;
    }
}

// ---------------------------------------------------------------------------
// Kernel B (fused): out[bc,h,w] = sum_p Bu[h,p] * T[bc,p,w]
//   grid = (H/ROWS, BC), 128 threads. Thread t owns w = 4t..4t+3.
//   Prologue: T[p][w4] computed in regs from K (smem) x Bv rows (regs).
//   Main loop: packed f32x2 FMA; Bu duplicated as (b,b) 64-bit pairs in smem.
// ---------------------------------------------------------------------------
__global__ __launch_bounds__(128) void fused_stage(const float* __restrict__ K,
                                                   float* __restrict__ out) {
    int bc = blockIdx.y;
    int h0 = blockIdx.x * ROWS;
    int t = threadIdx.x;

    __shared__ float sK[PP * QQ];
    __shared__ unsigned long long sBu2[ROWS * PP];  // (b,b) pairs, 16 KB

    // Stage K[bc] (256 floats)
    sK[t] = K[(size_t)bc * (PP * QQ) + t];
    sK[t + 128] = K[(size_t)bc * (PP * QQ) + t + 128];

    // Stage duplicated Bu tile
    #pragma unroll
    for (int i = t; i < ROWS * PP; i += 128) {
        float b = g_Bu[h0 * PP + i];
        unsigned long long bb;
        asm("mov.b64 %0, {%1, %2};" : "=l"(bb) : "f"(b), "f"(b));
        sBu2[i] = bb;
    }

    // Load Bv rows for our 4 w columns (16 x LDG.128)
    float rv0[QQ], rv1[QQ], rv2[QQ], rv3[QQ];
    {
        const float4* bv = reinterpret_cast<const float4*>(g_Bv);
        #pragma unroll
        for (int j = 0; j < 4; ++j) {
            float4 v0 = bv[(4 * t + 0) * 4 + j];
            float4 v1 = bv[(4 * t + 1) * 4 + j];
            float4 v2 = bv[(4 * t + 2) * 4 + j];
            float4 v3 = bv[(4 * t + 3) * 4 + j];
            rv0[4 * j] = v0.x; rv0[4 * j + 1] = v0.y; rv0[4 * j + 2] = v0.z; rv0[4 * j + 3] = v0.w;
            rv1[4 * j] = v1.x; rv1[4 * j + 1] = v1.y; rv1[4 * j + 2] = v1.z; rv1[4 * j + 3] = v1.w;
            rv2[4 * j] = v2.x; rv2[4 * j + 1] = v2.y; rv2[4 * j + 2] = v2.z; rv2[4 * j + 3] = v2.w;
            rv3[4 * j] = v3.x; rv3[4 * j + 1] = v3.y; rv3[4 * j + 2] = v3.z; rv3[4 * j + 3] = v3.w;
        }
    }
    __syncthreads();

    // Prologue: T[p][w4] = sum_q K[p][q] * Bv[w][q]; pack into f32x2 pairs
    unsigned long long Txy[PP], Tzw[PP];
    #pragma unroll
    for (int p = 0; p < PP; ++p) {
        float ax = 0.f, ay = 0.f, az = 0.f, aw = 0.f;
        #pragma unroll
        for (int q = 0; q < QQ; ++q) {
            float k = sK[p * QQ + q];
            ax = fmaf(k, rv0[q], ax);
            ay = fmaf(k, rv1[q], ay);
            az = fmaf(k, rv2[q], az);
            aw = fmaf(k, rv3[q], aw);
        }
        asm("mov.b64 %0, {%1, %2};" : "=l"(Txy[p]) : "f"(ax), "f"(ay));
        asm("mov.b64 %0, {%1, %2};" : "=l"(Tzw[p]) : "f"(az), "f"(aw));
    }

    float4* o = reinterpret_cast<float4*>(out + (size_t)bc * HH * WW + (size_t)h0 * WW);

    #pragma unroll 2
    for (int r = 0; r < ROWS; ++r) {
        unsigned long long axy = 0ull, azw = 0ull;
        #pragma unroll
        for (int p = 0; p < PP; ++p) {
            unsigned long long bb = sBu2[r * PP + p];  // LDS.64 broadcast
            asm("fma.rn.f32x2 %0, %1, %2, %0;" : "+l"(axy) : "l"(bb), "l"(Txy[p]));
            asm("fma.rn.f32x2 %0, %1, %2, %0;" : "+l"(azw) : "l"(bb), "l"(Tzw[p]));
        }
        float ox, oy, oz, ow;
        asm("mov.b64 {%0, %1}, %2;" : "=f"(ox), "=f"(oy) : "l"(axy));
        asm("mov.b64 {%0, %1}, %2;" : "=f"(oz), "=f"(ow) : "l"(azw));
        o[r * (WW / 4) + t] = make_float4(ox, oy, oz, ow);
    }
}

// ---------------------------------------------------------------------------
extern "C" void kernel_launch(void* const* d_in, const int* in_sizes, int n_in,
                              void* d_out, int out_size) {
    const float* K     = (const float*)d_in[0];
    const float* basis = (const float*)d_in[1];
    float* out = (float*)d_out;
    (void)in_sizes; (void)n_in; (void)out_size;

    extract_factors<<<96, 256>>>(basis);

    dim3 grid(HH / ROWS, BC);
    fused_stage<<<grid, 128>>>(K, out);
}